// round 5
// baseline (speedup 1.0000x reference)
#include <cuda_runtime.h>
#include <cstdint>

#define NB 256
#define NT 512
#define NC 64
#define NH 64
#define PITCH 68            // floats per smem row (bank-conflict padding)

// Projected q,k,v scratch. q is pre-scaled by 0.125 (exact exponent shift) and
// all three are stored rounded to tf32 (cvt.rna) so attention MMAs are unbiased.
__device__ float g_q[(size_t)NB * NT * NH];
__device__ float g_k[(size_t)NB * NT * NH];
__device__ float g_v[(size_t)NB * NT * NH];

__device__ __forceinline__ uint32_t smem_u32(const void* p) {
    uint32_t a;
    asm("{ .reg .u64 t; cvta.to.shared.u64 t, %1; cvt.u32.u64 %0, t; }"
        : "=r"(a) : "l"(p));
    return a;
}
__device__ __forceinline__ uint32_t f2tf32(float f) {
    uint32_t r;
    asm("cvt.rna.tf32.f32 %0, %1;" : "=r"(r) : "f"(f));
    return r;
}
__device__ __forceinline__ void mma_tf32(float c[4], const uint32_t a[4],
                                         uint32_t b0, uint32_t b1) {
    asm volatile(
        "mma.sync.aligned.m16n8k8.row.col.f32.tf32.tf32.f32 "
        "{%0,%1,%2,%3}, {%4,%5,%6,%7}, {%8,%9}, {%0,%1,%2,%3};"
        : "+f"(c[0]), "+f"(c[1]), "+f"(c[2]), "+f"(c[3])
        : "r"(a[0]), "r"(a[1]), "r"(a[2]), "r"(a[3]), "r"(b0), "r"(b1));
}
#define CP_ASYNC16(dst, src) \
    asm volatile("cp.async.cg.shared.global [%0], [%1], 16;" \
                 :: "r"((uint32_t)(dst)), "l"(src))
#define CP_COMMIT() asm volatile("cp.async.commit_group;" ::: "memory")
#define CP_WAIT0()  asm volatile("cp.async.wait_group 0;" ::: "memory")

// async-copy one 64x64 f32 tile (row-major, ld 64) into smem at pitch 68.
// 256 threads: 1024 16B chunks in 4 iterations.
__device__ __forceinline__ void load_tile64(uint32_t dst, const float* src, int tid) {
    #pragma unroll
    for (int m = 0; m < 4; m++) {
        int idx = tid + 256 * m;
        int r = idx >> 4, f4 = idx & 15;
        CP_ASYNC16(dst + r * (PITCH * 4) + f4 * 16, src + r * NH + f4 * 4);
    }
}

// smem byte offsets, kernel 2
#define K0OFF 0
#define K1OFF 17408
#define V0OFF 34816
#define V1OFF 52224
#define PQOFF 69632                 // Q staging (init) / per-warp P slices (loop)
#define SMEM2 104448
// kernel 1: x tile @0 (34816), W tiles @34816 (3 x 17408)
#define SMEM1 87040

// ---------------------------------------------------------------------------
// Kernel 1: q,k,v = x @ {Wq,Wk,Wv} via tf32 mma.sync.
// 256 threads = 8 warps, CTA = 128 rows; each warp owns 16 rows (1 m-frag).
// Wq is pre-scaled by 0.125 so attention needs no logit scaling.
// ---------------------------------------------------------------------------
__global__ void __launch_bounds__(256, 2) proj_kernel(
    const float* __restrict__ x,
    const float* __restrict__ wk,
    const float* __restrict__ wq,
    const float* __restrict__ wv)
{
    extern __shared__ char smraw[];
    float* smf = (float*)smraw;
    const int tid = threadIdx.x;
    const int w = tid >> 5, lane = tid & 31, g = lane >> 2, tig = lane & 3;
    const size_t r0 = (size_t)blockIdx.x * 128;

    // x tile -> smem, rounded to tf32 (128 rows x 64 = 2048 float4)
    #pragma unroll
    for (int m = 0; m < 8; m++) {
        int idx = tid + 256 * m;
        int r = idx >> 4, f4 = idx & 15;
        float4 v = *(const float4*)(x + (r0 + r) * NC + f4 * 4);
        uint4 u = make_uint4(f2tf32(v.x), f2tf32(v.y), f2tf32(v.z), f2tf32(v.w));
        *(uint4*)(smf + r * PITCH + f4 * 4) = u;
    }
    // W tiles -> smem, rounded; Wq scaled by 0.125 (exact).
    const float* W[3] = { wq, wk, wv };
    #pragma unroll
    for (int sel = 0; sel < 3; sel++) {
        float* ws = smf + (34816 + sel * 17408) / 4;
        const float scl = (sel == 0) ? 0.125f : 1.0f;
        #pragma unroll
        for (int m = 0; m < 4; m++) {
            int idx = tid + 256 * m;
            int r = idx >> 4, f4 = idx & 15;
            float4 v = *(const float4*)(W[sel] + r * NH + f4 * 4);
            uint4 u = make_uint4(f2tf32(v.x * scl), f2tf32(v.y * scl),
                                 f2tf32(v.z * scl), f2tf32(v.w * scl));
            *(uint4*)(ws + r * PITCH + f4 * 4) = u;
        }
    }
    __syncthreads();

    // A fragments: warp rows 16w+{g,g+8}, cols {tig,tig+4}+8t
    uint32_t xa[8][4];
    const uint32_t* smu = (const uint32_t*)smf;
    const int rr = 16 * w + g;
    #pragma unroll
    for (int t = 0; t < 8; t++) {
        xa[t][0] = smu[rr * PITCH + 8 * t + tig];
        xa[t][1] = smu[(rr + 8) * PITCH + 8 * t + tig];
        xa[t][2] = smu[rr * PITCH + 8 * t + tig + 4];
        xa[t][3] = smu[(rr + 8) * PITCH + 8 * t + tig + 4];
    }

    float* G[3] = { g_q, g_k, g_v };
    #pragma unroll
    for (int sel = 0; sel < 3; sel++) {
        const uint32_t* ws = (const uint32_t*)(smf + (34816 + sel * 17408) / 4);
        float cc[8][4] = {};
        #pragma unroll
        for (int t = 0; t < 8; t++)
            #pragma unroll
            for (int n = 0; n < 8; n++) {
                uint32_t b0 = ws[(8 * t + tig) * PITCH + 8 * n + g];
                uint32_t b1 = ws[(8 * t + tig + 4) * PITCH + 8 * n + g];
                mma_tf32(cc[n], xa[t], b0, b1);
            }
        const size_t row0 = r0 + rr;
        #pragma unroll
        for (int n = 0; n < 8; n++) {
            uint2 o0 = make_uint2(f2tf32(cc[n][0]), f2tf32(cc[n][1]));
            uint2 o1 = make_uint2(f2tf32(cc[n][2]), f2tf32(cc[n][3]));
            *(uint2*)(G[sel] + row0 * NH + 8 * n + 2 * tig) = o0;
            *(uint2*)(G[sel] + (row0 + 8) * NH + 8 * n + 2 * tig) = o1;
        }
    }
}

// ---------------------------------------------------------------------------
// Kernel 2: flash attention. CTA = (qt, b): 128 q-rows, key tiles of 64.
// 8 warps x 16 q-rows (1 m-frag each) -> ~110 live regs -> 2 CTAs/SM, 16 warps.
// S computed in two n-halves (sc[4][4] transient). O in regs across key tiles
// (softmax without max-subtraction; q pre-scaled by 0.125).
// ---------------------------------------------------------------------------
__global__ void __launch_bounds__(256, 2) attn_kernel(float* __restrict__ out)
{
    extern __shared__ char smraw[];
    float* smf = (float*)smraw;
    const uint32_t sb = smem_u32(smraw);
    const int tid = threadIdx.x;
    const int w = tid >> 5, lane = tid & 31, g = lane >> 2, tig = lane & 3;
    const int qt = blockIdx.x, b = blockIdx.y;
    const int nt = 2 * qt + 2;
    const size_t qbase = ((size_t)b * NT + (size_t)qt * 128) * NH;
    const float* kp0 = g_k + (size_t)b * NT * NH;
    const float* vp0 = g_v + (size_t)b * NT * NH;

    load_tile64(sb + K0OFF, kp0, tid);
    load_tile64(sb + V0OFF, vp0, tid);
    CP_COMMIT();

    // stage Q (tf32-rounded, pre-scaled), lift A-frags to regs
    float* PQ = smf + PQOFF / 4;
    #pragma unroll
    for (int m = 0; m < 8; m++) {
        int idx = tid + 256 * m;
        int r = idx >> 4, f4 = idx & 15;
        *(float4*)(PQ + r * PITCH + f4 * 4) =
            *(const float4*)(g_q + qbase + r * NH + f4 * 4);
    }
    __syncthreads();

    const int rr = 16 * w + g;
    uint32_t qa[8][4];
    {
        const uint32_t* qu = (const uint32_t*)PQ;
        #pragma unroll
        for (int t = 0; t < 8; t++) {
            qa[t][0] = qu[rr * PITCH + 8 * t + tig];
            qa[t][1] = qu[(rr + 8) * PITCH + 8 * t + tig];
            qa[t][2] = qu[rr * PITCH + 8 * t + tig + 4];
            qa[t][3] = qu[(rr + 8) * PITCH + 8 * t + tig + 4];
        }
    }

    float oc[8][4] = {};
    float lsum[2] = {};
    // per-warp private P slice: 16 rows
    uint32_t* Pw = (uint32_t*)(smf + PQOFF / 4 + (size_t)(16 * w) * PITCH);
    const int row0 = qt * 128 + rr;
    const int row1 = row0 + 8;

    for (int j = 0; j < nt; j++) {
        CP_WAIT0();
        __syncthreads();
        const int cur = j & 1;
        if (j + 1 < nt) {
            load_tile64(sb + (cur ? K0OFF : K1OFF), kp0 + (size_t)(j + 1) * 64 * NH, tid);
            load_tile64(sb + (cur ? V0OFF : V1OFF), vp0 + (size_t)(j + 1) * 64 * NH, tid);
            CP_COMMIT();
        }
        const uint32_t* Ks = (const uint32_t*)(smf + (cur ? K1OFF : K0OFF) / 4);
        const uint32_t* Vs = (const uint32_t*)(smf + (cur ? V1OFF : V0OFF) / 4);

        const int jbase = j * 64;
        const bool needMask = (j >= 2 * qt);

        // S = Q K^T in two n-halves (keeps transient regs low)
        #pragma unroll
        for (int h = 0; h < 2; h++) {
            float sc[4][4] = {};
            #pragma unroll
            for (int t = 0; t < 8; t++)
                #pragma unroll
                for (int n = 0; n < 4; n++) {
                    const int nn = 4 * h + n;
                    uint32_t b0 = Ks[(8 * nn + g) * PITCH + 8 * t + tig];
                    uint32_t b1 = Ks[(8 * nn + g) * PITCH + 8 * t + tig + 4];
                    mma_tf32(sc[n], qa[t], b0, b1);
                }
            // softmax (no max-sub; q pre-scaled) + causal mask + stage P
            #pragma unroll
            for (int n = 0; n < 4; n++) {
                const int nn = 4 * h + n;
                const int col = jbase + 8 * nn + 2 * tig;
                float e0 = __expf(sc[n][0]);
                float e1 = __expf(sc[n][1]);
                float e2 = __expf(sc[n][2]);
                float e3 = __expf(sc[n][3]);
                if (needMask) {
                    if (col > row0)     e0 = 0.f;
                    if (col + 1 > row0) e1 = 0.f;
                    if (col > row1)     e2 = 0.f;
                    if (col + 1 > row1) e3 = 0.f;
                }
                lsum[0] += e0 + e1;
                lsum[1] += e2 + e3;
                *(uint2*)(Pw + g * PITCH + 8 * nn + 2 * tig) =
                    make_uint2(f2tf32(e0), f2tf32(e1));
                *(uint2*)(Pw + (g + 8) * PITCH + 8 * nn + 2 * tig) =
                    make_uint2(f2tf32(e2), f2tf32(e3));
            }
        }
        __syncwarp();

        // O += P V
        #pragma unroll
        for (int t = 0; t < 8; t++) {
            uint32_t pa[4];
            pa[0] = Pw[g * PITCH + 8 * t + tig];
            pa[1] = Pw[(g + 8) * PITCH + 8 * t + tig];
            pa[2] = Pw[g * PITCH + 8 * t + tig + 4];
            pa[3] = Pw[(g + 8) * PITCH + 8 * t + tig + 4];
            #pragma unroll
            for (int n = 0; n < 8; n++) {
                uint32_t b0 = Vs[(8 * t + tig) * PITCH + 8 * n + g];
                uint32_t b1 = Vs[(8 * t + tig + 4) * PITCH + 8 * n + g];
                mma_tf32(oc[n], pa, b0, b1);
            }
        }
        __syncwarp();   // P reads done before next iteration overwrites
    }

    // reduce row sums across the quad, normalize, store
    float s0 = lsum[0];
    s0 += __shfl_xor_sync(0xffffffffu, s0, 1);
    s0 += __shfl_xor_sync(0xffffffffu, s0, 2);
    float s1 = lsum[1];
    s1 += __shfl_xor_sync(0xffffffffu, s1, 1);
    s1 += __shfl_xor_sync(0xffffffffu, s1, 2);
    const float inv0 = 1.0f / s0, inv1 = 1.0f / s1;
    #pragma unroll
    for (int n = 0; n < 8; n++) {
        float2 o0 = make_float2(oc[n][0] * inv0, oc[n][1] * inv0);
        float2 o1 = make_float2(oc[n][2] * inv1, oc[n][3] * inv1);
        *(float2*)(out + qbase + (size_t)rr * NH + 8 * n + 2 * tig) = o0;
        *(float2*)(out + qbase + (size_t)(rr + 8) * NH + 8 * n + 2 * tig) = o1;
    }
}

extern "C" void kernel_launch(void* const* d_in, const int* in_sizes, int n_in,
                              void* d_out, int out_size) {
    (void)in_sizes; (void)n_in; (void)out_size;
    const float* x  = (const float*)d_in[0];
    const float* wk = (const float*)d_in[1];
    const float* wq = (const float*)d_in[2];
    const float* wv = (const float*)d_in[3];
    float* out = (float*)d_out;

    cudaFuncSetAttribute(proj_kernel, cudaFuncAttributeMaxDynamicSharedMemorySize, SMEM1);
    cudaFuncSetAttribute(attn_kernel, cudaFuncAttributeMaxDynamicSharedMemorySize, SMEM2);

    proj_kernel<<<(NB * NT) / 128, 256, SMEM1>>>(x, wk, wq, wv);
    attn_kernel<<<dim3(NT / 128, NB), 256, SMEM2>>>(out);
}

// round 6
// speedup vs baseline: 2.0915x; 2.0915x over previous
#include <cuda_runtime.h>
#include <cuda_fp16.h>
#include <cstdint>

#define NB 256
#define NT 512
#define NC 64
#define NH 64
#define HP 72          // halves per smem row (pad: 144B rows, conflict-free ldmatrix)
#define HPB 144        // bytes per smem row

// Projected q,k,v scratch in fp16 (11-bit significand == tf32; half the HBM
// traffic). q pre-scaled by 0.125 (exact) so attention needs no logit scaling.
__device__ __half g_q[(size_t)NB * NT * NH];
__device__ __half g_k[(size_t)NB * NT * NH];
__device__ __half g_v[(size_t)NB * NT * NH];

__device__ __forceinline__ uint32_t smem_u32(const void* p) {
    uint32_t a;
    asm("{ .reg .u64 t; cvta.to.shared.u64 t, %1; cvt.u32.u64 %0, t; }"
        : "=r"(a) : "l"(p));
    return a;
}
__device__ __forceinline__ void mma_f16(float c[4], const uint32_t a[4],
                                        uint32_t b0, uint32_t b1) {
    asm volatile(
        "mma.sync.aligned.m16n8k16.row.col.f32.f16.f16.f32 "
        "{%0,%1,%2,%3}, {%4,%5,%6,%7}, {%8,%9}, {%0,%1,%2,%3};"
        : "+f"(c[0]), "+f"(c[1]), "+f"(c[2]), "+f"(c[3])
        : "r"(a[0]), "r"(a[1]), "r"(a[2]), "r"(a[3]), "r"(b0), "r"(b1));
}
__device__ __forceinline__ void ldsm4(uint32_t r[4], uint32_t addr) {
    asm volatile("ldmatrix.sync.aligned.m8n8.x4.shared.b16 {%0,%1,%2,%3}, [%4];"
        : "=r"(r[0]), "=r"(r[1]), "=r"(r[2]), "=r"(r[3]) : "r"(addr));
}
__device__ __forceinline__ void ldsm4t(uint32_t r[4], uint32_t addr) {
    asm volatile("ldmatrix.sync.aligned.m8n8.x4.trans.shared.b16 {%0,%1,%2,%3}, [%4];"
        : "=r"(r[0]), "=r"(r[1]), "=r"(r[2]), "=r"(r[3]) : "r"(addr));
}
// x4 address patterns (one 16B row address per lane), pitch HPB:
// A (row-major m16k16):  m0=(r0..7,k0..7) m1=(r8..15,k0..7) m2=(r0..7,k8..15) m3=(r8..15,k8..15)
__device__ __forceinline__ uint32_t addrA(uint32_t base, int lane, int row0, int k0) {
    return base + (uint32_t)(row0 + (lane & 15)) * HPB
                + (uint32_t)(k0 * 2 + ((lane >> 4) << 4));
}
// B from K rows (row-major [n][k], no trans): m0/m1 = b0/b1 of n-tile n0; m2/m3 of n0+8
__device__ __forceinline__ uint32_t addrB(uint32_t base, int lane, int n0, int k0) {
    return base + (uint32_t)(n0 + (lane & 7) + ((lane >> 4) << 3)) * HPB
                + (uint32_t)(k0 * 2 + (((lane >> 3) & 1) << 4));
}
// B from V/W rows (row-major [k][n], trans): m0/m1 = b0/b1 of n-tile n0; m2/m3 of n0+8
__device__ __forceinline__ uint32_t addrT(uint32_t base, int lane, int s0, int n0) {
    return base + (uint32_t)(s0 + (lane & 7) + (((lane >> 3) & 1) << 3)) * HPB
                + (uint32_t)(n0 * 2 + ((lane >> 4) << 4));
}
#define CP_ASYNC16(dst, src) \
    asm volatile("cp.async.cg.shared.global [%0], [%1], 16;" \
                 :: "r"((uint32_t)(dst)), "l"(src))
#define CP_COMMIT() asm volatile("cp.async.commit_group;" ::: "memory")
#define CP_WAIT0()  asm volatile("cp.async.wait_group 0;" ::: "memory")

// async-copy one 64x64 fp16 tile (row-major, ld 64) into smem (pitch HPB).
__device__ __forceinline__ void load_tile64(uint32_t dst, const __half* src, int tid) {
    #pragma unroll
    for (int m = 0; m < 4; m++) {
        int idx = tid + 128 * m;           // 512 16B chunks
        int r = idx >> 3, c = idx & 7;
        CP_ASYNC16(dst + r * HPB + c * 16, src + r * NH + c * 8);
    }
}

// attn smem byte offsets
#define K0OFF 0
#define K1OFF 9216
#define V0OFF 18432
#define V1OFF 27648
#define PQOFF 36864      // Q stage (128 rows, init) / per-warp P slices (loop)
#define SMEM2 55296
// proj: x rows 0-127, W_sel rows 128+64*sel  (320 rows total)
#define SMEM1 46080

// ---------------------------------------------------------------------------
// Kernel 1: q,k,v = x @ {Wq,Wk,Wv}, fp16 mma.sync m16n8k16 + ldmatrix.
// 128 threads = 4 warps; CTA = 128 rows; warp = 32 rows (2 m-frags).
// ---------------------------------------------------------------------------
__global__ void __launch_bounds__(128, 3) proj_kernel(
    const float* __restrict__ x,
    const float* __restrict__ wk,
    const float* __restrict__ wq,
    const float* __restrict__ wv)
{
    extern __shared__ char smraw[];
    __half* smh = (__half*)smraw;
    const uint32_t sb = smem_u32(smraw);
    const int tid = threadIdx.x;
    const int w = tid >> 5, lane = tid & 31, g = lane >> 2, tig = lane & 3;
    const size_t r0 = (size_t)blockIdx.x * 128;

    // x tile -> smem fp16 (2048 float4 chunks)
    #pragma unroll
    for (int m = 0; m < 16; m++) {
        int idx = tid + 128 * m;
        int r = idx >> 4, f4 = idx & 15;
        float4 v = *(const float4*)(x + (r0 + r) * NC + f4 * 4);
        *(__half2*)(smh + r * HP + f4 * 4)     = __floats2half2_rn(v.x, v.y);
        *(__half2*)(smh + r * HP + f4 * 4 + 2) = __floats2half2_rn(v.z, v.w);
    }
    // W tiles [c][n] -> smem fp16; Wq scaled by 0.125 (exact exponent shift)
    const float* W[3] = { wq, wk, wv };
    #pragma unroll
    for (int sel = 0; sel < 3; sel++) {
        __half* ws = smh + (128 + 64 * sel) * HP;
        const float scl = (sel == 0) ? 0.125f : 1.0f;
        #pragma unroll
        for (int m = 0; m < 8; m++) {
            int idx = tid + 128 * m;
            int r = idx >> 4, f4 = idx & 15;
            float4 v = *(const float4*)(W[sel] + r * NH + f4 * 4);
            *(__half2*)(ws + r * HP + f4 * 4)     = __floats2half2_rn(v.x * scl, v.y * scl);
            *(__half2*)(ws + r * HP + f4 * 4 + 2) = __floats2half2_rn(v.z * scl, v.w * scl);
        }
    }
    __syncthreads();

    // A fragments (x rows 32w..32w+31), 4 k16-steps
    uint32_t xa[2][4][4];
    #pragma unroll
    for (int mt = 0; mt < 2; mt++)
        #pragma unroll
        for (int t = 0; t < 4; t++)
            ldsm4(xa[mt][t], addrA(sb, lane, 32 * w + 16 * mt, 16 * t));

    __half* G[3] = { g_q, g_k, g_v };
    #pragma unroll
    for (int sel = 0; sel < 3; sel++) {
        const uint32_t wb = sb + (uint32_t)(128 + 64 * sel) * HPB;
        float cc[2][8][4] = {};
        #pragma unroll
        for (int t = 0; t < 4; t++)
            #pragma unroll
            for (int np = 0; np < 4; np++) {
                uint32_t br[4];
                ldsm4t(br, addrT(wb, lane, 16 * t, 16 * np));
                #pragma unroll
                for (int mt = 0; mt < 2; mt++) {
                    mma_f16(cc[mt][2 * np],     xa[mt][t], br[0], br[1]);
                    mma_f16(cc[mt][2 * np + 1], xa[mt][t], br[2], br[3]);
                }
            }
        #pragma unroll
        for (int mt = 0; mt < 2; mt++) {
            const size_t ra = r0 + 32 * w + 16 * mt + g;
            #pragma unroll
            for (int n = 0; n < 8; n++) {
                *(__half2*)(G[sel] + ra * NH + 8 * n + 2 * tig) =
                    __floats2half2_rn(cc[mt][n][0], cc[mt][n][1]);
                *(__half2*)(G[sel] + (ra + 8) * NH + 8 * n + 2 * tig) =
                    __floats2half2_rn(cc[mt][n][2], cc[mt][n][3]);
            }
        }
    }
}

// ---------------------------------------------------------------------------
// Kernel 2: flash attention, fp16 MMA + ldmatrix. CTA = (qt, b): 128 q-rows,
// key tiles of 64, 4 warps x 32 q-rows. O in fp32 regs across tiles
// (softmax without max-subtraction; q pre-scaled). K/V double-buffered cp.async.
// ---------------------------------------------------------------------------
__global__ void __launch_bounds__(128, 3) attn_kernel(float* __restrict__ out)
{
    extern __shared__ char smraw[];
    const uint32_t sb = smem_u32(smraw);
    const int tid = threadIdx.x;
    const int w = tid >> 5, lane = tid & 31, g = lane >> 2, tig = lane & 3;
    const int qt = (gridDim.x - 1) - blockIdx.x;   // big causal tiles first
    const int b = blockIdx.y;
    const int nt = 2 * qt + 2;
    const size_t qbase = ((size_t)b * NT + (size_t)qt * 128) * NH;
    const __half* kp0 = g_k + (size_t)b * NT * NH;
    const __half* vp0 = g_v + (size_t)b * NT * NH;

    load_tile64(sb + K0OFF, kp0, tid);
    load_tile64(sb + V0OFF, vp0, tid);
    CP_COMMIT();

    // stage Q (fp16, pre-scaled) -> lift A-frags
    #pragma unroll
    for (int m = 0; m < 8; m++) {
        int idx = tid + 128 * m;                   // 1024 16B chunks
        int r = idx >> 3, c = idx & 7;
        *(uint4*)(smraw + PQOFF + r * HPB + c * 16) =
            *(const uint4*)(g_q + qbase + r * NH + c * 8);
    }
    __syncthreads();

    uint32_t qa[2][4][4];
    #pragma unroll
    for (int mt = 0; mt < 2; mt++)
        #pragma unroll
        for (int t = 0; t < 4; t++)
            ldsm4(qa[mt][t], addrA(sb + PQOFF, lane, 32 * w + 16 * mt, 16 * t));
    __syncthreads();   // everyone done reading Q before P overwrites it

    float oc[2][8][4] = {};
    float lsum[2][2] = {};
    const uint32_t Pb = sb + PQOFF + (uint32_t)w * (32 * HPB);   // warp P slice
    __half* Ph = (__half*)(smraw + PQOFF) + (size_t)w * (32 * HP);
    const int row0q = qt * 128 + 32 * w + g;

    for (int j = 0; j < nt; j++) {
        CP_WAIT0();
        __syncthreads();
        const int cur = j & 1;
        if (j + 1 < nt) {
            load_tile64(sb + (cur ? K0OFF : K1OFF), kp0 + (size_t)(j + 1) * 64 * NH, tid);
            load_tile64(sb + (cur ? V0OFF : V1OFF), vp0 + (size_t)(j + 1) * 64 * NH, tid);
            CP_COMMIT();
        }
        const uint32_t Kb = sb + (cur ? K1OFF : K0OFF);
        const uint32_t Vb = sb + (cur ? V1OFF : V0OFF);
        const int jbase = j * 64;
        const bool needMask = (j >= 2 * qt);

        // S = Q K^T, two n-tiles (one np) at a time; softmax; stage P as fp16
        #pragma unroll
        for (int np = 0; np < 4; np++) {
            float sc[2][2][4] = {};
            #pragma unroll
            for (int t = 0; t < 4; t++) {
                uint32_t kr[4];
                ldsm4(kr, addrB(Kb, lane, 16 * np, 16 * t));
                mma_f16(sc[0][0], qa[0][t], kr[0], kr[1]);
                mma_f16(sc[0][1], qa[0][t], kr[2], kr[3]);
                mma_f16(sc[1][0], qa[1][t], kr[0], kr[1]);
                mma_f16(sc[1][1], qa[1][t], kr[2], kr[3]);
            }
            #pragma unroll
            for (int mt = 0; mt < 2; mt++) {
                const int r0 = row0q + 16 * mt, r1 = r0 + 8;
                #pragma unroll
                for (int h = 0; h < 2; h++) {
                    const int nn = 2 * np + h;
                    const int col = jbase + 8 * nn + 2 * tig;
                    float e0 = __expf(sc[mt][h][0]);
                    float e1 = __expf(sc[mt][h][1]);
                    float e2 = __expf(sc[mt][h][2]);
                    float e3 = __expf(sc[mt][h][3]);
                    if (needMask) {
                        if (col > r0)     e0 = 0.f;
                        if (col + 1 > r0) e1 = 0.f;
                        if (col > r1)     e2 = 0.f;
                        if (col + 1 > r1) e3 = 0.f;
                    }
                    lsum[mt][0] += e0 + e1;
                    lsum[mt][1] += e2 + e3;
                    *(__half2*)(Ph + (16 * mt + g) * HP + 8 * nn + 2 * tig) =
                        __floats2half2_rn(e0, e1);
                    *(__half2*)(Ph + (16 * mt + g + 8) * HP + 8 * nn + 2 * tig) =
                        __floats2half2_rn(e2, e3);
                }
            }
        }
        __syncwarp();

        // O += P V
        #pragma unroll
        for (int t = 0; t < 4; t++) {
            uint32_t pa[2][4];
            ldsm4(pa[0], addrA(Pb, lane, 0, 16 * t));
            ldsm4(pa[1], addrA(Pb, lane, 16, 16 * t));
            #pragma unroll
            for (int np = 0; np < 4; np++) {
                uint32_t vr[4];
                ldsm4t(vr, addrT(Vb, lane, 16 * t, 16 * np));
                mma_f16(oc[0][2 * np],     pa[0], vr[0], vr[1]);
                mma_f16(oc[0][2 * np + 1], pa[0], vr[2], vr[3]);
                mma_f16(oc[1][2 * np],     pa[1], vr[0], vr[1]);
                mma_f16(oc[1][2 * np + 1], pa[1], vr[2], vr[3]);
            }
        }
        __syncwarp();   // P reads done before next tile overwrites
    }

    // reduce row sums over the quad (tig lanes), normalize, store fp32
    #pragma unroll
    for (int mt = 0; mt < 2; mt++) {
        float s0 = lsum[mt][0];
        s0 += __shfl_xor_sync(0xffffffffu, s0, 1);
        s0 += __shfl_xor_sync(0xffffffffu, s0, 2);
        float s1 = lsum[mt][1];
        s1 += __shfl_xor_sync(0xffffffffu, s1, 1);
        s1 += __shfl_xor_sync(0xffffffffu, s1, 2);
        const float inv0 = 1.0f / s0, inv1 = 1.0f / s1;
        const size_t ra = (size_t)(32 * w + 16 * mt + g);
        #pragma unroll
        for (int n = 0; n < 8; n++) {
            *(float2*)(out + qbase + ra * NH + 8 * n + 2 * tig) =
                make_float2(oc[mt][n][0] * inv0, oc[mt][n][1] * inv0);
            *(float2*)(out + qbase + (ra + 8) * NH + 8 * n + 2 * tig) =
                make_float2(oc[mt][n][2] * inv1, oc[mt][n][3] * inv1);
        }
    }
}

extern "C" void kernel_launch(void* const* d_in, const int* in_sizes, int n_in,
                              void* d_out, int out_size) {
    (void)in_sizes; (void)n_in; (void)out_size;
    const float* x  = (const float*)d_in[0];
    const float* wk = (const float*)d_in[1];
    const float* wq = (const float*)d_in[2];
    const float* wv = (const float*)d_in[3];
    float* out = (float*)d_out;

    cudaFuncSetAttribute(proj_kernel, cudaFuncAttributeMaxDynamicSharedMemorySize, SMEM1);
    cudaFuncSetAttribute(attn_kernel, cudaFuncAttributeMaxDynamicSharedMemorySize, SMEM2);

    proj_kernel<<<(NB * NT) / 128, 128, SMEM1>>>(x, wk, wq, wv);
    attn_kernel<<<dim3(NT / 128, NB), 128, SMEM2>>>(out);
}

// round 7
// speedup vs baseline: 2.1414x; 1.0238x over previous
#include <cuda_runtime.h>
#include <cuda_fp16.h>
#include <cstdint>

#define NB 256
#define NT 512
#define NC 64
#define NH 64
#define HP 72          // halves per smem row (pad: 144B rows, conflict-free ldmatrix)
#define HPB 144        // bytes per smem row

// Projected q,k,v scratch in fp16 (11-bit significand == tf32).
// q pre-scaled by 0.125*log2(e) so attention logits are in base-2 domain:
// softmax exp becomes a single ex2.approx.f32 (no FMUL).
__device__ __half g_q[(size_t)NB * NT * NH];
__device__ __half g_k[(size_t)NB * NT * NH];
__device__ __half g_v[(size_t)NB * NT * NH];

__device__ __forceinline__ uint32_t smem_u32(const void* p) {
    uint32_t a;
    asm("{ .reg .u64 t; cvta.to.shared.u64 t, %1; cvt.u32.u64 %0, t; }"
        : "=r"(a) : "l"(p));
    return a;
}
__device__ __forceinline__ float ex2f(float x) {
    float r;
    asm("ex2.approx.f32 %0, %1;" : "=f"(r) : "f"(x));
    return r;
}
__device__ __forceinline__ uint32_t packh2(float lo, float hi) {
    __half2 h = __floats2half2_rn(lo, hi);
    return *reinterpret_cast<uint32_t*>(&h);
}
__device__ __forceinline__ void mma_f16(float c[4], const uint32_t a[4],
                                        uint32_t b0, uint32_t b1) {
    asm volatile(
        "mma.sync.aligned.m16n8k16.row.col.f32.f16.f16.f32 "
        "{%0,%1,%2,%3}, {%4,%5,%6,%7}, {%8,%9}, {%0,%1,%2,%3};"
        : "+f"(c[0]), "+f"(c[1]), "+f"(c[2]), "+f"(c[3])
        : "r"(a[0]), "r"(a[1]), "r"(a[2]), "r"(a[3]), "r"(b0), "r"(b1));
}
__device__ __forceinline__ void ldsm4(uint32_t r[4], uint32_t addr) {
    asm volatile("ldmatrix.sync.aligned.m8n8.x4.shared.b16 {%0,%1,%2,%3}, [%4];"
        : "=r"(r[0]), "=r"(r[1]), "=r"(r[2]), "=r"(r[3]) : "r"(addr));
}
__device__ __forceinline__ void ldsm4t(uint32_t r[4], uint32_t addr) {
    asm volatile("ldmatrix.sync.aligned.m8n8.x4.trans.shared.b16 {%0,%1,%2,%3}, [%4];"
        : "=r"(r[0]), "=r"(r[1]), "=r"(r[2]), "=r"(r[3]) : "r"(addr));
}
// A (row-major m16k16): m0=(r0..7,k0..7) m1=(r8..15,k0..7) m2=(r0..7,k8..15) m3=(r8..15,k8..15)
__device__ __forceinline__ uint32_t addrA(uint32_t base, int lane, int row0, int k0) {
    return base + (uint32_t)(row0 + (lane & 15)) * HPB
                + (uint32_t)(k0 * 2 + ((lane >> 4) << 4));
}
// B from K rows (row-major [n][k], no trans)
__device__ __forceinline__ uint32_t addrB(uint32_t base, int lane, int n0, int k0) {
    return base + (uint32_t)(n0 + (lane & 7) + ((lane >> 4) << 3)) * HPB
                + (uint32_t)(k0 * 2 + (((lane >> 3) & 1) << 4));
}
// B from V/W rows (row-major [k][n], trans)
__device__ __forceinline__ uint32_t addrT(uint32_t base, int lane, int s0, int n0) {
    return base + (uint32_t)(s0 + (lane & 7) + (((lane >> 3) & 1) << 3)) * HPB
                + (uint32_t)(n0 * 2 + ((lane >> 4) << 4));
}
#define CP_ASYNC16(dst, src) \
    asm volatile("cp.async.cg.shared.global [%0], [%1], 16;" \
                 :: "r"((uint32_t)(dst)), "l"(src))
#define CP_COMMIT() asm volatile("cp.async.commit_group;" ::: "memory")
#define CP_WAIT0()  asm volatile("cp.async.wait_group 0;" ::: "memory")

__device__ __forceinline__ void load_tile64(uint32_t dst, const __half* src, int tid) {
    #pragma unroll
    for (int m = 0; m < 4; m++) {
        int idx = tid + 128 * m;
        int r = idx >> 3, c = idx & 7;
        CP_ASYNC16(dst + r * HPB + c * 16, src + r * NH + c * 8);
    }
}

// attn smem
#define K0OFF 0
#define K1OFF 9216
#define V0OFF 18432
#define V1OFF 27648
#define PQOFF 36864      // Q staging (init only; P lives in registers now)
#define SMEM2 55296
// proj: x rows 0-127, W_sel rows 128+64*sel (320 rows)
#define SMEM1 46080

// ---------------------------------------------------------------------------
// Kernel 1: q,k,v = x @ {Wq,Wk,Wv}. 512 CTAs x two 128-row halves;
// W tiles loaded to smem ONCE per CTA. Wq pre-scaled by 0.125*log2(e).
// ---------------------------------------------------------------------------
__global__ void __launch_bounds__(128, 3) proj_kernel(
    const float* __restrict__ x,
    const float* __restrict__ wk,
    const float* __restrict__ wq,
    const float* __restrict__ wv)
{
    extern __shared__ char smraw[];
    __half* smh = (__half*)smraw;
    const uint32_t sb = smem_u32(smraw);
    const int tid = threadIdx.x;
    const int w = tid >> 5, lane = tid & 31, g = lane >> 2, tig = lane & 3;

    // W tiles [c][n] -> smem fp16, once
    const float* W[3] = { wq, wk, wv };
    #pragma unroll
    for (int sel = 0; sel < 3; sel++) {
        __half* ws = smh + (128 + 64 * sel) * HP;
        const float scl = (sel == 0) ? 0.125f * 1.44269504088896f : 1.0f;
        #pragma unroll
        for (int m = 0; m < 8; m++) {
            int idx = tid + 128 * m;
            int r = idx >> 4, f4 = idx & 15;
            float4 v = *(const float4*)(W[sel] + r * NH + f4 * 4);
            *(__half2*)(ws + r * HP + f4 * 4)     = __floats2half2_rn(v.x * scl, v.y * scl);
            *(__half2*)(ws + r * HP + f4 * 4 + 2) = __floats2half2_rn(v.z * scl, v.w * scl);
        }
    }

    __half* G[3] = { g_q, g_k, g_v };
    #pragma unroll 1
    for (int h = 0; h < 2; h++) {
        const size_t r0 = (size_t)blockIdx.x * 256 + (size_t)h * 128;
        __syncthreads();   // h=0: W ready; h>0: prior ldsm(A) readers done
        #pragma unroll
        for (int m = 0; m < 16; m++) {
            int idx = tid + 128 * m;
            int r = idx >> 4, f4 = idx & 15;
            float4 v = *(const float4*)(x + (r0 + r) * NC + f4 * 4);
            *(__half2*)(smh + r * HP + f4 * 4)     = __floats2half2_rn(v.x, v.y);
            *(__half2*)(smh + r * HP + f4 * 4 + 2) = __floats2half2_rn(v.z, v.w);
        }
        __syncthreads();

        uint32_t xa[2][4][4];
        #pragma unroll
        for (int mt = 0; mt < 2; mt++)
            #pragma unroll
            for (int t = 0; t < 4; t++)
                ldsm4(xa[mt][t], addrA(sb, lane, 32 * w + 16 * mt, 16 * t));

        #pragma unroll
        for (int sel = 0; sel < 3; sel++) {
            const uint32_t wb = sb + (uint32_t)(128 + 64 * sel) * HPB;
            float cc[2][8][4] = {};
            #pragma unroll
            for (int t = 0; t < 4; t++)
                #pragma unroll
                for (int np = 0; np < 4; np++) {
                    uint32_t br[4];
                    ldsm4t(br, addrT(wb, lane, 16 * t, 16 * np));
                    #pragma unroll
                    for (int mt = 0; mt < 2; mt++) {
                        mma_f16(cc[mt][2 * np],     xa[mt][t], br[0], br[1]);
                        mma_f16(cc[mt][2 * np + 1], xa[mt][t], br[2], br[3]);
                    }
                }
            #pragma unroll
            for (int mt = 0; mt < 2; mt++) {
                const size_t ra = r0 + 32 * w + 16 * mt + g;
                #pragma unroll
                for (int n = 0; n < 8; n++) {
                    *(__half2*)(G[sel] + ra * NH + 8 * n + 2 * tig) =
                        __floats2half2_rn(cc[mt][n][0], cc[mt][n][1]);
                    *(__half2*)(G[sel] + (ra + 8) * NH + 8 * n + 2 * tig) =
                        __floats2half2_rn(cc[mt][n][2], cc[mt][n][3]);
                }
            }
        }
    }
}

// ---------------------------------------------------------------------------
// Kernel 2: flash attention. CTA = (qt, b): 128 q-rows, key tiles of 64,
// 4 warps x 32 q-rows. P NEVER touches smem: the QK C-fragment, after
// ex2 + f16x2 pack, IS the PV A-fragment (same thread->element map).
// ---------------------------------------------------------------------------
__global__ void __launch_bounds__(128, 3) attn_kernel(float* __restrict__ out)
{
    extern __shared__ char smraw[];
    const uint32_t sb = smem_u32(smraw);
    const int tid = threadIdx.x;
    const int w = tid >> 5, lane = tid & 31, g = lane >> 2, tig = lane & 3;
    const int qt = (gridDim.x - 1) - blockIdx.x;   // big causal tiles first
    const int b = blockIdx.y;
    const int nt = 2 * qt + 2;
    const size_t qbase = ((size_t)b * NT + (size_t)qt * 128) * NH;
    const __half* kp0 = g_k + (size_t)b * NT * NH;
    const __half* vp0 = g_v + (size_t)b * NT * NH;

    load_tile64(sb + K0OFF, kp0, tid);
    load_tile64(sb + V0OFF, vp0, tid);
    CP_COMMIT();

    // stage Q (fp16, pre-scaled) -> lift A-frags
    #pragma unroll
    for (int m = 0; m < 8; m++) {
        int idx = tid + 128 * m;
        int r = idx >> 3, c = idx & 7;
        *(uint4*)(smraw + PQOFF + r * HPB + c * 16) =
            *(const uint4*)(g_q + qbase + r * NH + c * 8);
    }
    __syncthreads();

    uint32_t qa[2][4][4];
    #pragma unroll
    for (int mt = 0; mt < 2; mt++)
        #pragma unroll
        for (int t = 0; t < 4; t++)
            ldsm4(qa[mt][t], addrA(sb + PQOFF, lane, 32 * w + 16 * mt, 16 * t));

    float oc[2][8][4] = {};
    float lsum[2][2] = {};
    const int row0q = qt * 128 + 32 * w + g;

    for (int j = 0; j < nt; j++) {
        CP_WAIT0();
        __syncthreads();
        const int cur = j & 1;
        if (j + 1 < nt) {
            load_tile64(sb + (cur ? K0OFF : K1OFF), kp0 + (size_t)(j + 1) * 64 * NH, tid);
            load_tile64(sb + (cur ? V0OFF : V1OFF), vp0 + (size_t)(j + 1) * 64 * NH, tid);
            CP_COMMIT();
        }
        const uint32_t Kb = sb + (cur ? K1OFF : K0OFF);
        const uint32_t Vb = sb + (cur ? V1OFF : V0OFF);
        const int jbase = j * 64;
        const bool needMask = (j >= 2 * qt);

        // S = Q K^T; exp2; pack to fp16 PV A-fragments entirely in registers.
        // pl[mt][nn] = rows g    x cols(2tig,2tig+1) of n-tile nn
        // ph[mt][nn] = rows g+8  x cols(2tig,2tig+1)
        uint32_t pl[2][8], ph[2][8];
        #pragma unroll
        for (int np = 0; np < 4; np++) {
            float sc[2][2][4] = {};
            #pragma unroll
            for (int t = 0; t < 4; t++) {
                uint32_t kr[4];
                ldsm4(kr, addrB(Kb, lane, 16 * np, 16 * t));
                mma_f16(sc[0][0], qa[0][t], kr[0], kr[1]);
                mma_f16(sc[0][1], qa[0][t], kr[2], kr[3]);
                mma_f16(sc[1][0], qa[1][t], kr[0], kr[1]);
                mma_f16(sc[1][1], qa[1][t], kr[2], kr[3]);
            }
            #pragma unroll
            for (int mt = 0; mt < 2; mt++) {
                const int r0 = row0q + 16 * mt, r1 = r0 + 8;
                #pragma unroll
                for (int hh = 0; hh < 2; hh++) {
                    const int nn = 2 * np + hh;
                    const int col = jbase + 8 * nn + 2 * tig;
                    float e0 = ex2f(sc[mt][hh][0]);
                    float e1 = ex2f(sc[mt][hh][1]);
                    float e2 = ex2f(sc[mt][hh][2]);
                    float e3 = ex2f(sc[mt][hh][3]);
                    if (needMask) {
                        if (col > r0)     e0 = 0.f;
                        if (col + 1 > r0) e1 = 0.f;
                        if (col > r1)     e2 = 0.f;
                        if (col + 1 > r1) e3 = 0.f;
                    }
                    lsum[mt][0] += e0 + e1;
                    lsum[mt][1] += e2 + e3;
                    pl[mt][nn] = packh2(e0, e1);
                    ph[mt][nn] = packh2(e2, e3);
                }
            }
        }

        // O += P V  (A from registers; B via ldmatrix.trans)
        #pragma unroll
        for (int t = 0; t < 4; t++) {
            const uint32_t pa0[4] = { pl[0][2*t], ph[0][2*t], pl[0][2*t+1], ph[0][2*t+1] };
            const uint32_t pa1[4] = { pl[1][2*t], ph[1][2*t], pl[1][2*t+1], ph[1][2*t+1] };
            #pragma unroll
            for (int np = 0; np < 4; np++) {
                uint32_t vr[4];
                ldsm4t(vr, addrT(Vb, lane, 16 * t, 16 * np));
                mma_f16(oc[0][2 * np],     pa0, vr[0], vr[1]);
                mma_f16(oc[0][2 * np + 1], pa0, vr[2], vr[3]);
                mma_f16(oc[1][2 * np],     pa1, vr[0], vr[1]);
                mma_f16(oc[1][2 * np + 1], pa1, vr[2], vr[3]);
            }
        }
    }

    // reduce row sums over the quad, normalize, store fp32
    #pragma unroll
    for (int mt = 0; mt < 2; mt++) {
        float s0 = lsum[mt][0];
        s0 += __shfl_xor_sync(0xffffffffu, s0, 1);
        s0 += __shfl_xor_sync(0xffffffffu, s0, 2);
        float s1 = lsum[mt][1];
        s1 += __shfl_xor_sync(0xffffffffu, s1, 1);
        s1 += __shfl_xor_sync(0xffffffffu, s1, 2);
        const float inv0 = 1.0f / s0, inv1 = 1.0f / s1;
        const size_t ra = (size_t)(32 * w + 16 * mt + g);
        #pragma unroll
        for (int n = 0; n < 8; n++) {
            *(float2*)(out + qbase + ra * NH + 8 * n + 2 * tig) =
                make_float2(oc[mt][n][0] * inv0, oc[mt][n][1] * inv0);
            *(float2*)(out + qbase + (ra + 8) * NH + 8 * n + 2 * tig) =
                make_float2(oc[mt][n][2] * inv1, oc[mt][n][3] * inv1);
        }
    }
}

extern "C" void kernel_launch(void* const* d_in, const int* in_sizes, int n_in,
                              void* d_out, int out_size) {
    (void)in_sizes; (void)n_in; (void)out_size;
    const float* x  = (const float*)d_in[0];
    const float* wk = (const float*)d_in[1];
    const float* wq = (const float*)d_in[2];
    const float* wv = (const float*)d_in[3];
    float* out = (float*)d_out;

    cudaFuncSetAttribute(proj_kernel, cudaFuncAttributeMaxDynamicSharedMemorySize, SMEM1);
    cudaFuncSetAttribute(attn_kernel, cudaFuncAttributeMaxDynamicSharedMemorySize, SMEM2);

    proj_kernel<<<(NB * NT) / 256, 128, SMEM1>>>(x, wk, wq, wv);
    attn_kernel<<<dim3(NT / 128, NB), 128, SMEM2>>>(out);
}